// round 6
// baseline (speedup 1.0000x reference)
#include <cuda_runtime.h>
#include <math.h>

// Problem constants (fixed by setup_inputs)
#define N_NODES 4096
#define IN_DIM  512
#define H_DIM   256
#define OUTD    64
#define MAXDEG  192
#define EPSV    1e-8f
#define A_SCAD  3.7f
#define PROP_STEP 4
#define NBLK    148           // <= SM count: all blocks co-resident -> grid barrier safe

static const float LAMF = (float)(1.0 / 0.9 - 1.0);   // 1/LAM_HAT - 1

// ---------------- device scratch (static, no allocation) ----------------
__device__ float g_dsq [N_NODES];
__device__ float g_rdsq[N_NODES];
__device__ int   g_cnt[N_NODES];
__device__ int   g_cols[N_NODES * MAXDEG];
__device__ float g_y   [N_NODES * MAXDEG];
__device__ float g_Fu  [N_NODES * OUTD];
__device__ float g_F0  [N_NODES * OUTD];
__device__ float g_FA  [N_NODES * OUTD];
__device__ float g_FB  [N_NODES * OUTD];
__device__ float g_H   [N_NODES * H_DIM];
__device__ unsigned g_hist0[PROP_STEP][256];
__device__ unsigned g_selh [PROP_STEP][3][512];
__device__ int      g_M;
__device__ int          g_bar_count;
__device__ volatile int g_bar_phase;

// ---------------- grid barrier (requires all blocks co-resident) ------------
__device__ __forceinline__ void grid_bar() {
    __syncthreads();
    if (threadIdx.x == 0) {
        __threadfence();
        int gen = g_bar_phase;
        if (atomicAdd(&g_bar_count, 1) == NBLK - 1) {
            g_bar_count = 0;
            __threadfence();
            g_bar_phase = gen + 1;
        } else {
            while (g_bar_phase == gen) __nanosleep(64);
        }
        __threadfence();
    }
    __syncthreads();
}

// ---------------- reset ----------------
__global__ void reset_kernel() {
    int i = threadIdx.x;
    if (i == 0) { g_M = 0; g_bar_count = 0; g_bar_phase = 0; }
    for (int j = i; j < PROP_STEP * 256; j += blockDim.x) ((unsigned*)g_hist0)[j] = 0;
    for (int j = i; j < PROP_STEP * 3 * 512; j += blockDim.x) ((unsigned*)g_selh)[j] = 0;
}

// ---------------- build padded adjacency (deterministic, column-sorted) ----
__global__ __launch_bounds__(256) void build_kernel(const float* __restrict__ A) {
    __shared__ unsigned char sbit[N_NODES];
    __shared__ int scnt[256];
    int row = blockIdx.x, tid = threadIdx.x;
    const float* Arow = A + (size_t)row * N_NODES;
    for (int i = tid; i < N_NODES; i += 256) sbit[i] = (Arow[i] != 0.0f);
    __syncthreads();
    int c0 = tid * 16;
    int cnt = 0;
#pragma unroll
    for (int c = 0; c < 16; c++) cnt += sbit[c0 + c];
    scnt[tid] = cnt;
    __syncthreads();
    for (int off = 1; off < 256; off <<= 1) {
        int v = (tid >= off) ? scnt[tid - off] : 0;
        __syncthreads();
        scnt[tid] += v;
        __syncthreads();
    }
    int base  = scnt[tid] - cnt;
    int total = scnt[255];
    int pos = base;
    for (int c = 0; c < 16; c++)
        if (sbit[c0 + c] && pos < MAXDEG) g_cols[row * MAXDEG + (pos++)] = c0 + c;
    int t = min(total, MAXDEG);
    // one-time +inf padding of g_y (never rewritten; sorts past all real y)
    for (int e = t + tid; e < MAXDEG; e += 256)
        g_y[row * MAXDEG + e] = __int_as_float(0x7f800000);
    if (tid == 0) {
        g_cnt[row] = t;
        float d = sqrtf((float)(total + 1));      // D = deg + self-loop
        g_dsq[row]  = d;
        g_rdsq[row] = 1.0f / d;
        atomicAdd(&g_M, t);
    }
}

// ---------------- software-pipelined fp32 GEMM1: H = relu(X @ W1 + b1) ------
__global__ __launch_bounds__(256) void gemm1_kernel(const float* __restrict__ A,
                                                    const float* __restrict__ B,
                                                    const float* __restrict__ bias,
                                                    float* __restrict__ C) {
    const int N = H_DIM, K = IN_DIM;
    __shared__ float As[16][64];
    __shared__ float Bs[16][64];
    int tid = threadIdx.x;
    int tx = tid & 15, ty = tid >> 4;
    int row0 = blockIdx.y * 64, col0 = blockIdx.x * 64;
    int ar = tid >> 2, ak = (tid & 3) * 4;
    int bk = tid >> 4, bc = (tid & 15) * 4;
    const float* Aptr = A + (size_t)(row0 + ar) * K + ak;
    const float* Bptr = B + (size_t)bk * N + col0 + bc;

    float acc[4][4];
#pragma unroll
    for (int i = 0; i < 4; i++)
#pragma unroll
        for (int j = 0; j < 4; j++) acc[i][j] = 0.0f;

    float4 av = *(const float4*)Aptr;
    float4 bv = *(const float4*)Bptr;

    for (int k0 = 0; k0 < K; k0 += 16) {
        As[ak + 0][ar] = av.x; As[ak + 1][ar] = av.y;
        As[ak + 2][ar] = av.z; As[ak + 3][ar] = av.w;
        *(float4*)&Bs[bk][bc] = bv;
        __syncthreads();
        if (k0 + 16 < K) {
            av = *(const float4*)(Aptr + k0 + 16);
            bv = *(const float4*)(Bptr + (size_t)(k0 + 16) * N);
        }
#pragma unroll
        for (int kk = 0; kk < 16; kk++) {
            float4 a = *(float4*)&As[kk][ty * 4];
            float4 b = *(float4*)&Bs[kk][tx * 4];
            float avr[4] = {a.x, a.y, a.z, a.w};
            float bvr[4] = {b.x, b.y, b.z, b.w};
#pragma unroll
            for (int i = 0; i < 4; i++)
#pragma unroll
                for (int j = 0; j < 4; j++) acc[i][j] = fmaf(avr[i], bvr[j], acc[i][j]);
        }
        __syncthreads();
    }
#pragma unroll
    for (int i = 0; i < 4; i++) {
        int r = row0 + ty * 4 + i;
        float4 o;
        o.x = fmaxf(acc[i][0] + bias[col0 + tx * 4 + 0], 0.0f);
        o.y = fmaxf(acc[i][1] + bias[col0 + tx * 4 + 1], 0.0f);
        o.z = fmaxf(acc[i][2] + bias[col0 + tx * 4 + 2], 0.0f);
        o.w = fmaxf(acc[i][3] + bias[col0 + tx * 4 + 3], 0.0f);
        *(float4*)&C[(size_t)r * N + col0 + tx * 4] = o;
    }
}

// ------ GEMM2 fused: F0 = H @ W2 + b2 ; Fu = rownorm(F0 / dsq) --------------
__global__ __launch_bounds__(256) void gemm2_fused_kernel(const float* __restrict__ A,
                                                          const float* __restrict__ B,
                                                          const float* __restrict__ bias) {
    const int N = OUTD, K = H_DIM;
    __shared__ float As[16][64];
    __shared__ float Bs[16][64];
    int tid = threadIdx.x;
    int tx = tid & 15, ty = tid >> 4;
    int row0 = blockIdx.y * 64;
    int ar = tid >> 2, ak = (tid & 3) * 4;
    int bk = tid >> 4, bc = (tid & 15) * 4;
    const float* Aptr = A + (size_t)(row0 + ar) * K + ak;
    const float* Bptr = B + (size_t)bk * N + bc;

    float acc[4][4];
#pragma unroll
    for (int i = 0; i < 4; i++)
#pragma unroll
        for (int j = 0; j < 4; j++) acc[i][j] = 0.0f;

    float4 av = *(const float4*)Aptr;
    float4 bv = *(const float4*)Bptr;

    for (int k0 = 0; k0 < K; k0 += 16) {
        As[ak + 0][ar] = av.x; As[ak + 1][ar] = av.y;
        As[ak + 2][ar] = av.z; As[ak + 3][ar] = av.w;
        *(float4*)&Bs[bk][bc] = bv;
        __syncthreads();
        if (k0 + 16 < K) {
            av = *(const float4*)(Aptr + k0 + 16);
            bv = *(const float4*)(Bptr + (size_t)(k0 + 16) * N);
        }
#pragma unroll
        for (int kk = 0; kk < 16; kk++) {
            float4 a = *(float4*)&As[kk][ty * 4];
            float4 b = *(float4*)&Bs[kk][tx * 4];
            float avr[4] = {a.x, a.y, a.z, a.w};
            float bvr[4] = {b.x, b.y, b.z, b.w};
#pragma unroll
            for (int i = 0; i < 4; i++)
#pragma unroll
                for (int j = 0; j < 4; j++) acc[i][j] = fmaf(avr[i], bvr[j], acc[i][j]);
        }
        __syncthreads();
    }
#pragma unroll
    for (int i = 0; i < 4; i++) {
        int r = row0 + ty * 4 + i;
        float4 o;
        o.x = acc[i][0] + bias[tx * 4 + 0];
        o.y = acc[i][1] + bias[tx * 4 + 1];
        o.z = acc[i][2] + bias[tx * 4 + 2];
        o.w = acc[i][3] + bias[tx * 4 + 3];
        *(float4*)&g_F0[r * OUTD + tx * 4] = o;
        float d = g_dsq[r];
        float vx = o.x / d, vy = o.y / d, vz = o.z / d, vw = o.w / d;
        float p = vx * vx + vy * vy + vz * vz + vw * vw;
#pragma unroll
        for (int off = 8; off; off >>= 1) p += __shfl_xor_sync(0xffffffffu, p, off);
        float inv = 1.0f / fmaxf(sqrtf(p), EPSV);
        float4 fo;
        fo.x = vx * inv; fo.y = vy * inv; fo.z = vz * inv; fo.w = vw * inv;
        *(float4*)&g_Fu[r * OUTD + tx * 4] = fo;
    }
}

// ---------------- the persistent iteration kernel ----------------------------
__global__ __launch_bounds__(256) void mega_kernel(const float* __restrict__ lg0,
                                                   const float* __restrict__ rdec,
                                                   const float* __restrict__ ralpha,
                                                   float* __restrict__ out) {
    __shared__ unsigned hist[256];
    __shared__ unsigned h[512];
    __shared__ unsigned sscan[256];
    __shared__ unsigned sprefix[2];
    __shared__ int      srank[2];
    __shared__ float    red2[4][2];

    const int tid  = threadIdx.x, b = blockIdx.x;
    const int lane = tid & 31, warp = tid >> 5;

    const float g0 = expf(lg0[0]);
    const float rr = 1.0f / (1.0f + expf(-rdec[0]));
    const float al = 1.0f / (1.0f + expf(-ralpha[0]));
    const float lam = LAMF;

    const int M = g_M;
    double idx = 0.75 * (double)(M - 1);
    long k0l = (long)floor(idx);
    const float frac = (float)(idx - (double)k0l);
    const int R0 = (int)k0l;
    long k1l = k0l + 1; if (k1l > (long)(M - 1)) k1l = M - 1;
    const int R1 = (int)k1l;

    for (int k = 0; k < PROP_STEP; k++) {
        const float* Fin = (k == 0) ? g_F0 : ((k & 1) ? g_FA : g_FB);
        float* Fout = (k == PROP_STEP - 1) ? out : ((k & 1) ? g_FB : g_FA);

        // ================= Y phase: warp per row, 4-way edge ILP =============
        hist[tid] = 0;
        __syncthreads();
        for (int r = b * 8 + warp; r < N_NODES; r += NBLK * 8) {
            float fa = g_Fu[r * OUTD + lane];
            float fb = g_Fu[r * OUTD + lane + 32];
            const int* cols = g_cols + r * MAXDEG;
            float* yrow = g_y + r * MAXDEG;
            int cnt = g_cnt[r];
            for (int e = 0; e < cnt; e += 4) {
                int e2 = min(e + 1, cnt - 1);
                int e3 = min(e + 2, cnt - 1);
                int e4 = min(e + 3, cnt - 1);
                int j1 = cols[e]  * OUTD;
                int j2 = cols[e2] * OUTD;
                int j3 = cols[e3] * OUTD;
                int j4 = cols[e4] * OUTD;
                float p1 = fa * g_Fu[j1 + lane] + fb * g_Fu[j1 + lane + 32];
                float p2 = fa * g_Fu[j2 + lane] + fb * g_Fu[j2 + lane + 32];
                float p3 = fa * g_Fu[j3 + lane] + fb * g_Fu[j3 + lane + 32];
                float p4 = fa * g_Fu[j4 + lane] + fb * g_Fu[j4 + lane + 32];
#pragma unroll
                for (int o = 16; o; o >>= 1) {
                    p1 += __shfl_xor_sync(0xffffffffu, p1, o);
                    p2 += __shfl_xor_sync(0xffffffffu, p2, o);
                    p3 += __shfl_xor_sync(0xffffffffu, p3, o);
                    p4 += __shfl_xor_sync(0xffffffffu, p4, o);
                }
                if (lane == 0) {
                    float y1 = fminf(fmaxf(1.0f - p1, 0.0f), 2.0f);
                    yrow[e] = y1;
                    atomicAdd(&hist[__float_as_uint(y1) >> 24], 1u);
                    if (e + 1 < cnt) {
                        float y2 = fminf(fmaxf(1.0f - p2, 0.0f), 2.0f);
                        yrow[e + 1] = y2;
                        atomicAdd(&hist[__float_as_uint(y2) >> 24], 1u);
                    }
                    if (e + 2 < cnt) {
                        float y3 = fminf(fmaxf(1.0f - p3, 0.0f), 2.0f);
                        yrow[e + 2] = y3;
                        atomicAdd(&hist[__float_as_uint(y3) >> 24], 1u);
                    }
                    if (e + 3 < cnt) {
                        float y4 = fminf(fmaxf(1.0f - p4, 0.0f), 2.0f);
                        yrow[e + 3] = y4;
                        atomicAdd(&hist[__float_as_uint(y4) >> 24], 1u);
                    }
                }
            }
        }
        __syncthreads();
        if (hist[tid]) atomicAdd(&g_hist0[k][tid], hist[tid]);
        grid_bar();   // y + hist0 complete

        // ============ S phase: exact 0.75-quantile -> lamc (per-block) =======
        float lamc;
        {
            float gp = g0 * powf(rr, (float)k);
            float gd;
            if (M <= 0) {
                gd = 1.0f;
            } else {
                // level-0: scan g_hist0[k]
                unsigned c = g_hist0[k][tid];
                sscan[tid] = c;
                __syncthreads();
                for (int off = 1; off < 256; off <<= 1) {
                    unsigned v = (tid >= off) ? sscan[tid - off] : 0;
                    __syncthreads();
                    sscan[tid] += v;
                    __syncthreads();
                }
                {
                    unsigned incl = sscan[tid], excl = incl - c;
                    if ((unsigned)R0 >= excl && (unsigned)R0 < incl) { sprefix[0] = (unsigned)tid << 24; srank[0] = R0 - (int)excl; }
                    if ((unsigned)R1 >= excl && (unsigned)R1 < incl) { sprefix[1] = (unsigned)tid << 24; srank[1] = R1 - (int)excl; }
                }
                __syncthreads();
                unsigned p0 = sprefix[0], p1 = sprefix[1];
                int r0 = srank[0], r1 = srank[1];
                __syncthreads();

                const int SH[3] = {16, 8, 0};
#pragma unroll
                for (int p = 0; p < 3; p++) {
                    int sh = SH[p];
                    unsigned hm = (sh == 16) ? 0xFF000000u : (sh == 8) ? 0xFFFF0000u : 0xFFFFFF00u;
                    h[tid] = 0; h[tid + 256] = 0;
                    __syncthreads();
                    const int T = N_NODES * MAXDEG;
                    for (int s = b * 256 + tid; s < T; s += NBLK * 256) {
                        unsigned u = __float_as_uint(g_y[s]);
                        unsigned bb = (u >> sh) & 0xFFu;
                        if ((u & hm) == p0) atomicAdd(&h[bb], 1u);
                        if ((u & hm) == p1) atomicAdd(&h[256 + bb], 1u);
                    }
                    __syncthreads();
                    if (h[tid])       atomicAdd(&g_selh[k][p][tid], h[tid]);
                    if (h[tid + 256]) atomicAdd(&g_selh[k][p][tid + 256], h[tid + 256]);
                    grid_bar();
                    for (int t2 = 0; t2 < 2; t2++) {
                        unsigned cc = g_selh[k][p][t2 * 256 + tid];
                        sscan[tid] = cc;
                        __syncthreads();
                        for (int off = 1; off < 256; off <<= 1) {
                            unsigned v = (tid >= off) ? sscan[tid - off] : 0;
                            __syncthreads();
                            sscan[tid] += v;
                            __syncthreads();
                        }
                        unsigned incl = sscan[tid], excl = incl - cc;
                        int r = (t2 == 0) ? r0 : r1;
                        if ((unsigned)r >= excl && (unsigned)r < incl) {
                            sprefix[t2] = ((t2 == 0) ? p0 : p1) | ((unsigned)tid << sh);
                            srank[t2] = r - (int)excl;
                        }
                        __syncthreads();
                    }
                    p0 = sprefix[0]; p1 = sprefix[1];
                    r0 = srank[0];   r1 = srank[1];
                    __syncthreads();
                }
                float v0 = __uint_as_float(p0);
                float v1 = __uint_as_float(p1);
                gd = fmaxf(v0 * (1.0f - frac) + v1 * frac, EPSV);
            }
            lamc = al * (gp / A_SCAD) + (1.0f - al) * (gd / A_SCAD);
        }

        // ======== P phase: 4 independent 64-thread groups, no shared =========
        {
            const int g = tid >> 6, t = tid & 63;
            const int wg = (tid >> 5) & 1;
            const float alim = A_SCAD * lamc;
            const float wden = (A_SCAD - 1.0f);
            for (int r = b * 4 + g; r < N_NODES; r += NBLK * 4) {
                int cnt = g_cnt[r];
                float rdi = g_rdsq[r];
                const int*   cols = g_cols + r * MAXDEG;
                const float* yrow = g_y + r * MAXDEG;
                float S = 0.0f;
                float a0 = 0.0f, a1 = 0.0f, a2 = 0.0f, a3 = 0.0f;
                int e = 0;
                for (; e + 4 <= cnt; e += 4) {
                    int j0 = cols[e], j1 = cols[e + 1], j2 = cols[e + 2], j3 = cols[e + 3];
                    float y0 = yrow[e], y1 = yrow[e + 1], y2 = yrow[e + 2], y3 = yrow[e + 3];
                    float w0 = (y0 <= lamc) ? 1.0f : ((y0 <= alim) ? (alim - y0) / (wden * fmaxf(y0, EPSV)) : 0.0f);
                    float w1 = (y1 <= lamc) ? 1.0f : ((y1 <= alim) ? (alim - y1) / (wden * fmaxf(y1, EPSV)) : 0.0f);
                    float w2 = (y2 <= lamc) ? 1.0f : ((y2 <= alim) ? (alim - y2) / (wden * fmaxf(y2, EPSV)) : 0.0f);
                    float w3 = (y3 <= lamc) ? 1.0f : ((y3 <= alim) ? (alim - y3) / (wden * fmaxf(y3, EPSV)) : 0.0f);
                    S += (w0 + w1) + (w2 + w3);
                    a0 = fmaf(w0 * rdi * g_rdsq[j0], Fin[j0 * OUTD + t], a0);
                    a1 = fmaf(w1 * rdi * g_rdsq[j1], Fin[j1 * OUTD + t], a1);
                    a2 = fmaf(w2 * rdi * g_rdsq[j2], Fin[j2 * OUTD + t], a2);
                    a3 = fmaf(w3 * rdi * g_rdsq[j3], Fin[j3 * OUTD + t], a3);
                }
                for (; e < cnt; e++) {
                    int j = cols[e];
                    float y = yrow[e];
                    float w = (y <= lamc) ? 1.0f : ((y <= alim) ? (alim - y) / (wden * fmaxf(y, EPSV)) : 0.0f);
                    S += w;
                    a0 = fmaf(w * rdi * g_rdsq[j], Fin[j * OUTD + t], a0);
                }
                float acc = (a0 + a1) + (a2 + a3);
                float Q = S / (float)(cnt + 1) + lam;
                float f0 = g_F0[r * OUTD + t];
                float outv = acc / Q + lam * f0 / Q;
                Fout[r * OUTD + t] = outv;

                if (k < PROP_STEP - 1) {   // fused normalize for next iteration
                    float v = outv / g_dsq[r];
                    float s2 = v * v;
#pragma unroll
                    for (int o = 16; o; o >>= 1) s2 += __shfl_xor_sync(0xffffffffu, s2, o);
                    if (lane == 0) red2[g][wg] = s2;
                    asm volatile("bar.sync %0, %1;" :: "r"(g + 1), "r"(64) : "memory");
                    float nrm = sqrtf(red2[g][0] + red2[g][1]);
                    g_Fu[r * OUTD + t] = v / fmaxf(nrm, EPSV);
                    asm volatile("bar.sync %0, %1;" :: "r"(g + 1), "r"(64) : "memory");
                }
            }
        }
        if (k < PROP_STEP - 1) grid_bar();   // Fout/Fu visible before next Y
    }
}

// ---------------- host launcher ---------------------------------------------
extern "C" void kernel_launch(void* const* d_in, const int* in_sizes, int n_in,
                              void* d_out, int out_size) {
    const float* A      = (const float*)d_in[0];
    const float* X      = (const float*)d_in[1];
    const float* W1     = (const float*)d_in[2];
    const float* b1     = (const float*)d_in[3];
    const float* W2     = (const float*)d_in[4];
    const float* b2     = (const float*)d_in[5];
    const float* lg0    = (const float*)d_in[6];
    const float* rdec   = (const float*)d_in[7];
    const float* ralpha = (const float*)d_in[8];
    float* out = (float*)d_out;

    float* pH;
    cudaGetSymbolAddress((void**)&pH, g_H);

    reset_kernel<<<1, 1024>>>();
    build_kernel<<<N_NODES, 256>>>(A);
    gemm1_kernel<<<dim3(H_DIM / 64, N_NODES / 64), 256>>>(X, W1, b1, pH);
    gemm2_fused_kernel<<<dim3(1, N_NODES / 64), 256>>>(pH, W2, b2);
    mega_kernel<<<NBLK, 256>>>(lg0, rdec, ralpha, out);
}

// round 7
// speedup vs baseline: 1.9936x; 1.9936x over previous
#include <cuda_runtime.h>
#include <math.h>

// Problem constants (fixed by setup_inputs)
#define N_NODES 4096
#define IN_DIM  512
#define H_DIM   256
#define OUTD    64
#define MAXDEG  192
#define EPSV    1e-8f
#define A_SCAD  3.7f
#define PROP_STEP 4
#define NBLK    148           // <= SM count: all blocks co-resident -> grid barrier safe

static const float LAMF = (float)(1.0 / 0.9 - 1.0);   // 1/LAM_HAT - 1

// ---------------- device scratch (static, no allocation) ----------------
__device__ float g_dsq [N_NODES];
__device__ float g_rdsq[N_NODES];
__device__ int   g_cnt[N_NODES];
__device__ int   g_cols[N_NODES * MAXDEG];
__device__ float g_y   [N_NODES * MAXDEG];
__device__ float g_Fu  [N_NODES * OUTD];
__device__ float g_F0  [N_NODES * OUTD];
__device__ float g_FA  [N_NODES * OUTD];
__device__ float g_FB  [N_NODES * OUTD];
__device__ float g_H   [N_NODES * H_DIM];
__device__ unsigned g_hist0[PROP_STEP][256];
__device__ unsigned g_selh [PROP_STEP][3][512];
__device__ int      g_M;
__device__ int          g_bar_count;
__device__ volatile int g_bar_phase;

// ---------------- grid barrier (requires all blocks co-resident) ------------
__device__ __forceinline__ void grid_bar() {
    __syncthreads();
    if (threadIdx.x == 0) {
        __threadfence();
        int gen = g_bar_phase;
        if (atomicAdd(&g_bar_count, 1) == NBLK - 1) {
            g_bar_count = 0;
            __threadfence();
            g_bar_phase = gen + 1;
        } else {
            while (g_bar_phase == gen) __nanosleep(64);
        }
        __threadfence();
    }
    __syncthreads();
}

// ---------------- reset ----------------
__global__ void reset_kernel() {
    int i = threadIdx.x;
    if (i == 0) { g_M = 0; g_bar_count = 0; g_bar_phase = 0; }
    for (int j = i; j < PROP_STEP * 256; j += blockDim.x) ((unsigned*)g_hist0)[j] = 0;
    for (int j = i; j < PROP_STEP * 3 * 512; j += blockDim.x) ((unsigned*)g_selh)[j] = 0;
}

// ---------------- build padded adjacency (deterministic, column-sorted) ----
__global__ __launch_bounds__(256) void build_kernel(const float* __restrict__ A) {
    __shared__ unsigned char sbit[N_NODES];
    __shared__ int scnt[256];
    int row = blockIdx.x, tid = threadIdx.x;
    const float* Arow = A + (size_t)row * N_NODES;
    for (int i = tid; i < N_NODES; i += 256) sbit[i] = (Arow[i] != 0.0f);
    __syncthreads();
    int c0 = tid * 16;
    int cnt = 0;
#pragma unroll
    for (int c = 0; c < 16; c++) cnt += sbit[c0 + c];
    scnt[tid] = cnt;
    __syncthreads();
    for (int off = 1; off < 256; off <<= 1) {
        int v = (tid >= off) ? scnt[tid - off] : 0;
        __syncthreads();
        scnt[tid] += v;
        __syncthreads();
    }
    int base  = scnt[tid] - cnt;
    int total = scnt[255];
    int pos = base;
    for (int c = 0; c < 16; c++)
        if (sbit[c0 + c] && pos < MAXDEG) g_cols[row * MAXDEG + (pos++)] = c0 + c;
    int t = min(total, MAXDEG);
    for (int e = t + tid; e < MAXDEG; e += 256)
        g_y[row * MAXDEG + e] = __int_as_float(0x7f800000);   // +inf padding
    if (tid == 0) {
        g_cnt[row] = t;
        float d = sqrtf((float)(total + 1));      // D = deg + self-loop
        g_dsq[row]  = d;
        g_rdsq[row] = 1.0f / d;
        atomicAdd(&g_M, t);
    }
}

// ---------------- software-pipelined fp32 GEMM1: H = relu(X @ W1 + b1) ------
__global__ __launch_bounds__(256) void gemm1_kernel(const float* __restrict__ A,
                                                    const float* __restrict__ B,
                                                    const float* __restrict__ bias,
                                                    float* __restrict__ C) {
    const int N = H_DIM, K = IN_DIM;
    __shared__ float As[16][64];
    __shared__ float Bs[16][64];
    int tid = threadIdx.x;
    int tx = tid & 15, ty = tid >> 4;
    int row0 = blockIdx.y * 64, col0 = blockIdx.x * 64;
    int ar = tid >> 2, ak = (tid & 3) * 4;
    int bk = tid >> 4, bc = (tid & 15) * 4;
    const float* Aptr = A + (size_t)(row0 + ar) * K + ak;
    const float* Bptr = B + (size_t)bk * N + col0 + bc;

    float acc[4][4];
#pragma unroll
    for (int i = 0; i < 4; i++)
#pragma unroll
        for (int j = 0; j < 4; j++) acc[i][j] = 0.0f;

    float4 av = *(const float4*)Aptr;
    float4 bv = *(const float4*)Bptr;

    for (int k0 = 0; k0 < K; k0 += 16) {
        As[ak + 0][ar] = av.x; As[ak + 1][ar] = av.y;
        As[ak + 2][ar] = av.z; As[ak + 3][ar] = av.w;
        *(float4*)&Bs[bk][bc] = bv;
        __syncthreads();
        if (k0 + 16 < K) {
            av = *(const float4*)(Aptr + k0 + 16);
            bv = *(const float4*)(Bptr + (size_t)(k0 + 16) * N);
        }
#pragma unroll
        for (int kk = 0; kk < 16; kk++) {
            float4 a = *(float4*)&As[kk][ty * 4];
            float4 b = *(float4*)&Bs[kk][tx * 4];
            float avr[4] = {a.x, a.y, a.z, a.w};
            float bvr[4] = {b.x, b.y, b.z, b.w};
#pragma unroll
            for (int i = 0; i < 4; i++)
#pragma unroll
                for (int j = 0; j < 4; j++) acc[i][j] = fmaf(avr[i], bvr[j], acc[i][j]);
        }
        __syncthreads();
    }
#pragma unroll
    for (int i = 0; i < 4; i++) {
        int r = row0 + ty * 4 + i;
        float4 o;
        o.x = fmaxf(acc[i][0] + bias[col0 + tx * 4 + 0], 0.0f);
        o.y = fmaxf(acc[i][1] + bias[col0 + tx * 4 + 1], 0.0f);
        o.z = fmaxf(acc[i][2] + bias[col0 + tx * 4 + 2], 0.0f);
        o.w = fmaxf(acc[i][3] + bias[col0 + tx * 4 + 3], 0.0f);
        *(float4*)&C[(size_t)r * N + col0 + tx * 4] = o;
    }
}

// ------ GEMM2 fused: F0 = H @ W2 + b2 ; Fu = rownorm(F0 / dsq) --------------
__global__ __launch_bounds__(256) void gemm2_fused_kernel(const float* __restrict__ A,
                                                          const float* __restrict__ B,
                                                          const float* __restrict__ bias) {
    const int N = OUTD, K = H_DIM;
    __shared__ float As[16][64];
    __shared__ float Bs[16][64];
    int tid = threadIdx.x;
    int tx = tid & 15, ty = tid >> 4;
    int row0 = blockIdx.y * 64;
    int ar = tid >> 2, ak = (tid & 3) * 4;
    int bk = tid >> 4, bc = (tid & 15) * 4;
    const float* Aptr = A + (size_t)(row0 + ar) * K + ak;
    const float* Bptr = B + (size_t)bk * N + bc;

    float acc[4][4];
#pragma unroll
    for (int i = 0; i < 4; i++)
#pragma unroll
        for (int j = 0; j < 4; j++) acc[i][j] = 0.0f;

    float4 av = *(const float4*)Aptr;
    float4 bv = *(const float4*)Bptr;

    for (int k0 = 0; k0 < K; k0 += 16) {
        As[ak + 0][ar] = av.x; As[ak + 1][ar] = av.y;
        As[ak + 2][ar] = av.z; As[ak + 3][ar] = av.w;
        *(float4*)&Bs[bk][bc] = bv;
        __syncthreads();
        if (k0 + 16 < K) {
            av = *(const float4*)(Aptr + k0 + 16);
            bv = *(const float4*)(Bptr + (size_t)(k0 + 16) * N);
        }
#pragma unroll
        for (int kk = 0; kk < 16; kk++) {
            float4 a = *(float4*)&As[kk][ty * 4];
            float4 b = *(float4*)&Bs[kk][tx * 4];
            float avr[4] = {a.x, a.y, a.z, a.w};
            float bvr[4] = {b.x, b.y, b.z, b.w};
#pragma unroll
            for (int i = 0; i < 4; i++)
#pragma unroll
                for (int j = 0; j < 4; j++) acc[i][j] = fmaf(avr[i], bvr[j], acc[i][j]);
        }
        __syncthreads();
    }
#pragma unroll
    for (int i = 0; i < 4; i++) {
        int r = row0 + ty * 4 + i;
        float4 o;
        o.x = acc[i][0] + bias[tx * 4 + 0];
        o.y = acc[i][1] + bias[tx * 4 + 1];
        o.z = acc[i][2] + bias[tx * 4 + 2];
        o.w = acc[i][3] + bias[tx * 4 + 3];
        *(float4*)&g_F0[r * OUTD + tx * 4] = o;
        float d = g_dsq[r];
        float vx = o.x / d, vy = o.y / d, vz = o.z / d, vw = o.w / d;
        float p = vx * vx + vy * vy + vz * vz + vw * vw;
#pragma unroll
        for (int off = 8; off; off >>= 1) p += __shfl_xor_sync(0xffffffffu, p, off);
        float inv = 1.0f / fmaxf(sqrtf(p), EPSV);
        float4 fo;
        fo.x = vx * inv; fo.y = vy * inv; fo.z = vz * inv; fo.w = vw * inv;
        *(float4*)&g_Fu[r * OUTD + tx * 4] = fo;
    }
}

// ---------------- persistent iteration kernel: 1024 threads/block -----------
__global__ __launch_bounds__(1024, 1)
void mega_kernel(const float* __restrict__ lg0,
                 const float* __restrict__ rdec,
                 const float* __restrict__ ralpha,
                 float* __restrict__ out) {
    __shared__ unsigned hist[256];
    __shared__ unsigned h[512];
    __shared__ unsigned sscan[256];
    __shared__ unsigned sprefix[2];
    __shared__ int      srank[2];

    const int tid  = threadIdx.x, b = blockIdx.x;
    const int lane = tid & 31, warp = tid >> 5;
    const int myrow = warp * NBLK + b;          // balanced warp->row map, one row/warp

    const float g0 = expf(lg0[0]);
    const float rr = 1.0f / (1.0f + expf(-rdec[0]));
    const float al = 1.0f / (1.0f + expf(-ralpha[0]));
    const float lam = LAMF;

    const int M = g_M;
    double idx = 0.75 * (double)(M - 1);
    long k0l = (long)floor(idx);
    const float frac = (float)(idx - (double)k0l);
    const int R0 = (int)k0l;
    long k1l = k0l + 1; if (k1l > (long)(M - 1)) k1l = M - 1;
    const int R1 = (int)k1l;

    // row-invariant loads for Y/P phases
    int   cnt = 0; float rdi = 0.0f, di = 1.0f; const int* cols = g_cols;
    if (myrow < N_NODES) {
        cnt  = g_cnt[myrow];
        rdi  = g_rdsq[myrow];
        di   = g_dsq[myrow];
        cols = g_cols + myrow * MAXDEG;
    }

    for (int k = 0; k < PROP_STEP; k++) {
        const float* Fin = (k == 0) ? g_F0 : ((k & 1) ? g_FA : g_FB);
        float* Fout = (k == PROP_STEP - 1) ? out : ((k & 1) ? g_FB : g_FA);

        // ================= Y phase: one row per warp, 4-way edge ILP =========
        if (tid < 256) hist[tid] = 0;
        __syncthreads();
        if (myrow < N_NODES) {
            float fa = g_Fu[myrow * OUTD + lane];
            float fb = g_Fu[myrow * OUTD + lane + 32];
            float* yrow = g_y + myrow * MAXDEG;
            for (int e = 0; e < cnt; e += 4) {
                int e2 = min(e + 1, cnt - 1);
                int e3 = min(e + 2, cnt - 1);
                int e4 = min(e + 3, cnt - 1);
                int j1 = cols[e]  * OUTD;
                int j2 = cols[e2] * OUTD;
                int j3 = cols[e3] * OUTD;
                int j4 = cols[e4] * OUTD;
                float p1 = fa * g_Fu[j1 + lane] + fb * g_Fu[j1 + lane + 32];
                float p2 = fa * g_Fu[j2 + lane] + fb * g_Fu[j2 + lane + 32];
                float p3 = fa * g_Fu[j3 + lane] + fb * g_Fu[j3 + lane + 32];
                float p4 = fa * g_Fu[j4 + lane] + fb * g_Fu[j4 + lane + 32];
#pragma unroll
                for (int o = 16; o; o >>= 1) {
                    p1 += __shfl_xor_sync(0xffffffffu, p1, o);
                    p2 += __shfl_xor_sync(0xffffffffu, p2, o);
                    p3 += __shfl_xor_sync(0xffffffffu, p3, o);
                    p4 += __shfl_xor_sync(0xffffffffu, p4, o);
                }
                if (lane == 0) {
                    float y1 = fminf(fmaxf(1.0f - p1, 0.0f), 2.0f);
                    yrow[e] = y1;
                    atomicAdd(&hist[__float_as_uint(y1) >> 24], 1u);
                    if (e + 1 < cnt) {
                        float y2 = fminf(fmaxf(1.0f - p2, 0.0f), 2.0f);
                        yrow[e + 1] = y2;
                        atomicAdd(&hist[__float_as_uint(y2) >> 24], 1u);
                    }
                    if (e + 2 < cnt) {
                        float y3 = fminf(fmaxf(1.0f - p3, 0.0f), 2.0f);
                        yrow[e + 2] = y3;
                        atomicAdd(&hist[__float_as_uint(y3) >> 24], 1u);
                    }
                    if (e + 3 < cnt) {
                        float y4 = fminf(fmaxf(1.0f - p4, 0.0f), 2.0f);
                        yrow[e + 3] = y4;
                        atomicAdd(&hist[__float_as_uint(y4) >> 24], 1u);
                    }
                }
            }
        }
        __syncthreads();
        if (tid < 256 && hist[tid]) atomicAdd(&g_hist0[k][tid], hist[tid]);
        grid_bar();   // y + hist0 complete

        // ============ S phase: exact 0.75-quantile -> lamc (per-block) =======
        float lamc;
        {
            float gp = g0 * powf(rr, (float)k);
            float gd;
            if (M <= 0) {
                gd = 1.0f;
            } else {
                // level-0 scan of g_hist0[k] (first 256 threads; barrier-safe)
                unsigned c = 0;
                if (tid < 256) { c = g_hist0[k][tid]; sscan[tid] = c; }
                __syncthreads();
                for (int off = 1; off < 256; off <<= 1) {
                    unsigned v = 0;
                    if (tid < 256 && tid >= off) v = sscan[tid - off];
                    __syncthreads();
                    if (tid < 256) sscan[tid] += v;
                    __syncthreads();
                }
                if (tid < 256) {
                    unsigned incl = sscan[tid], excl = incl - c;
                    if ((unsigned)R0 >= excl && (unsigned)R0 < incl) { sprefix[0] = (unsigned)tid << 24; srank[0] = R0 - (int)excl; }
                    if ((unsigned)R1 >= excl && (unsigned)R1 < incl) { sprefix[1] = (unsigned)tid << 24; srank[1] = R1 - (int)excl; }
                }
                __syncthreads();
                unsigned p0 = sprefix[0], p1 = sprefix[1];
                int r0 = srank[0], r1 = srank[1];
                __syncthreads();

                const int SH[3] = {16, 8, 0};
#pragma unroll
                for (int p = 0; p < 3; p++) {
                    int sh = SH[p];
                    unsigned hm = (sh == 16) ? 0xFF000000u : (sh == 8) ? 0xFFFF0000u : 0xFFFFFF00u;
                    if (tid < 512) h[tid] = 0;
                    __syncthreads();
                    const int T = N_NODES * MAXDEG;
                    for (int s = b * 1024 + tid; s < T; s += NBLK * 1024) {
                        unsigned u = __float_as_uint(g_y[s]);
                        unsigned bb = (u >> sh) & 0xFFu;
                        if ((u & hm) == p0) atomicAdd(&h[bb], 1u);
                        if ((u & hm) == p1) atomicAdd(&h[256 + bb], 1u);
                    }
                    __syncthreads();
                    if (tid < 512 && h[tid]) atomicAdd(&g_selh[k][p][tid], h[tid]);
                    grid_bar();
                    for (int t2 = 0; t2 < 2; t2++) {
                        unsigned cc = 0;
                        if (tid < 256) { cc = g_selh[k][p][t2 * 256 + tid]; sscan[tid] = cc; }
                        __syncthreads();
                        for (int off = 1; off < 256; off <<= 1) {
                            unsigned v = 0;
                            if (tid < 256 && tid >= off) v = sscan[tid - off];
                            __syncthreads();
                            if (tid < 256) sscan[tid] += v;
                            __syncthreads();
                        }
                        if (tid < 256) {
                            unsigned incl = sscan[tid], excl = incl - cc;
                            int r = (t2 == 0) ? r0 : r1;
                            if ((unsigned)r >= excl && (unsigned)r < incl) {
                                sprefix[t2] = ((t2 == 0) ? p0 : p1) | ((unsigned)tid << sh);
                                srank[t2] = r - (int)excl;
                            }
                        }
                        __syncthreads();
                    }
                    p0 = sprefix[0]; p1 = sprefix[1];
                    r0 = srank[0];   r1 = srank[1];
                    __syncthreads();
                }
                float v0 = __uint_as_float(p0);
                float v1 = __uint_as_float(p1);
                gd = fmaxf(v0 * (1.0f - frac) + v1 * frac, EPSV);
            }
            lamc = al * (gp / A_SCAD) + (1.0f - al) * (gd / A_SCAD);
        }

        // ======== P phase: one row per warp; lane owns cols lane, lane+32 ====
        if (myrow < N_NODES) {
            const float alim = A_SCAD * lamc;
            const float wden = (A_SCAD - 1.0f);
            const float* yrow = g_y + myrow * MAXDEG;
            float S = 0.0f;
            float a0 = 0.0f, a1 = 0.0f;     // col = lane
            float c0 = 0.0f, c1 = 0.0f;     // col = lane + 32
            int e = 0;
            for (; e + 2 <= cnt; e += 2) {
                int j0 = cols[e], j1 = cols[e + 1];
                float y0 = yrow[e], y1 = yrow[e + 1];
                float w0 = (y0 <= lamc) ? 1.0f : ((y0 <= alim) ? (alim - y0) / (wden * fmaxf(y0, EPSV)) : 0.0f);
                float w1 = (y1 <= lamc) ? 1.0f : ((y1 <= alim) ? (alim - y1) / (wden * fmaxf(y1, EPSV)) : 0.0f);
                S += w0 + w1;
                float sc0 = w0 * rdi * g_rdsq[j0];
                float sc1 = w1 * rdi * g_rdsq[j1];
                a0 = fmaf(sc0, Fin[j0 * OUTD + lane],      a0);
                c0 = fmaf(sc0, Fin[j0 * OUTD + lane + 32], c0);
                a1 = fmaf(sc1, Fin[j1 * OUTD + lane],      a1);
                c1 = fmaf(sc1, Fin[j1 * OUTD + lane + 32], c1);
            }
            if (e < cnt) {
                int j = cols[e];
                float y = yrow[e];
                float w = (y <= lamc) ? 1.0f : ((y <= alim) ? (alim - y) / (wden * fmaxf(y, EPSV)) : 0.0f);
                S += w;
                float sc = w * rdi * g_rdsq[j];
                a0 = fmaf(sc, Fin[j * OUTD + lane],      a0);
                c0 = fmaf(sc, Fin[j * OUTD + lane + 32], c0);
            }
            float Q = S / (float)(cnt + 1) + lam;
            float f0lo = g_F0[myrow * OUTD + lane];
            float f0hi = g_F0[myrow * OUTD + lane + 32];
            float olo = (a0 + a1) / Q + lam * f0lo / Q;
            float ohi = (c0 + c1) / Q + lam * f0hi / Q;
            Fout[myrow * OUTD + lane]      = olo;
            Fout[myrow * OUTD + lane + 32] = ohi;

            if (k < PROP_STEP - 1) {        // fused normalize for next iteration
                float vlo = olo / di, vhi = ohi / di;
                float s2 = vlo * vlo + vhi * vhi;
#pragma unroll
                for (int o = 16; o; o >>= 1) s2 += __shfl_xor_sync(0xffffffffu, s2, o);
                float inv = 1.0f / fmaxf(sqrtf(s2), EPSV);
                g_Fu[myrow * OUTD + lane]      = vlo * inv;
                g_Fu[myrow * OUTD + lane + 32] = vhi * inv;
            }
        }
        if (k < PROP_STEP - 1) grid_bar();   // Fout/Fu visible before next Y
    }
}

// ---------------- host launcher ---------------------------------------------
extern "C" void kernel_launch(void* const* d_in, const int* in_sizes, int n_in,
                              void* d_out, int out_size) {
    const float* A      = (const float*)d_in[0];
    const float* X      = (const float*)d_in[1];
    const float* W1     = (const float*)d_in[2];
    const float* b1     = (const float*)d_in[3];
    const float* W2     = (const float*)d_in[4];
    const float* b2     = (const float*)d_in[5];
    const float* lg0    = (const float*)d_in[6];
    const float* rdec   = (const float*)d_in[7];
    const float* ralpha = (const float*)d_in[8];
    float* out = (float*)d_out;

    float* pH;
    cudaGetSymbolAddress((void**)&pH, g_H);

    reset_kernel<<<1, 1024>>>();
    build_kernel<<<N_NODES, 256>>>(A);
    gemm1_kernel<<<dim3(H_DIM / 64, N_NODES / 64), 256>>>(X, W1, b1, pH);
    gemm2_fused_kernel<<<dim3(1, N_NODES / 64), 256>>>(pH, W2, b2);
    mega_kernel<<<NBLK, 1024>>>(lg0, rdec, ralpha, out);
}